// round 16
// baseline (speedup 1.0000x reference)
#include <cuda_runtime.h>
#include <cstdint>
#include <math.h>

// AFMADEBlock: incremental triangular evaluation of the MADE autoregressive
// inverse. One degree-group finalized per step (31 steps).
//
// R16 = R15 + net-split warp pairs. 7 pairs {mu-warp, lv-warp} x 4 rows + 1
// producer warp (480 thr, grid 147). Per-SM weight traffic unchanged
// (14 x half-set = 7 sets) but warps/SMSP 2.25 -> 3.75 and the per-warp
// serial chain halves — R15 showed the binder is exposed per-warp latency
// (issue 41%, nothing saturated). Cross-net emit exchange via double-
// buffered smem, ordered by the phase barrier (odd t) / pair barrier (even).

#define Dd 32
#define Bb 4096
#define RPW 4                  // rows per warp pair
#define NPAIR 7                // warp pairs per block
#define NCW (2 * NPAIR)        // 14 compute warps
#define THREADS ((NCW + 1) * 32)       // 480
#define ROWS_PER_BLOCK (NPAIR * RPW)   // 28
#define GRID 147               // 147*28 = 4116 >= 4096

#define STEP_FLOATS 5696       // per-step staged weights (2 nets)
#define W1OFF 512
#define W2OFF 5120

// Permuted+masked weights (hidden units sorted by degree). ~656KB, static.
__device__ __align__(16) float g_W0p[2][32][256];
__device__ __align__(16) float g_W1p[2][256][256];
__device__ __align__(16) float g_W2p[2][256][32];
__device__ __align__(16) float g_b0p[2][256];
__device__ __align__(16) float g_b1p[2][256];
__device__ __align__(16) float g_b2[2][32];

__device__ __forceinline__ int degS(int k) {
    return (k < 72) ? (k / 9 + 1) : ((k - 72) / 8 + 9);
}
__device__ __forceinline__ int permS(int k) {
    int d, jj;
    if (k < 72) { d = k / 9 + 1;        jj = k % 9; }
    else        { d = (k - 72) / 8 + 9; jj = (k - 72) % 8; }
    return (d - 1) + 31 * jj;   // original index of k-th sorted unit
}

__global__ void prep_kernel(
    const float* __restrict__ mu_W0, const float* __restrict__ mu_b0,
    const float* __restrict__ mu_W1, const float* __restrict__ mu_b1,
    const float* __restrict__ mu_W2, const float* __restrict__ mu_b2,
    const float* __restrict__ lv_W0, const float* __restrict__ lv_b0,
    const float* __restrict__ lv_W1, const float* __restrict__ lv_b1,
    const float* __restrict__ lv_W2, const float* __restrict__ lv_b2)
{
    int idx = blockIdx.x * blockDim.x + threadIdx.x;
    if (idx >= 2 * 256 * 256) return;
    int net = idx >> 16;
    int k   = (idx >> 8) & 255;   // sorted hidden row
    int c   = idx & 255;          // sorted hidden col

    const float* W0 = net ? lv_W0 : mu_W0;
    const float* b0 = net ? lv_b0 : mu_b0;
    const float* W1 = net ? lv_W1 : mu_W1;
    const float* b1 = net ? lv_b1 : mu_b1;
    const float* W2 = net ? lv_W2 : mu_W2;
    const float* b2 = net ? lv_b2 : mu_b2;

    int dk = degS(k), pk = permS(k);
    int dc = degS(c), pc = permS(c);

    g_W1p[net][k][c] = (dc >= dk) ? W1[pk * 256 + pc] : 0.f;
    if (k < 32) g_W0p[net][k][c] = (dc >= (k + 1)) ? W0[k * 256 + pc] : 0.f;
    if (c < 32) g_W2p[net][k][c] = ((c + 1) > dk) ? W2[pk * 32 + c] : 0.f;
    if (k == 0) {
        g_b0p[net][c] = b0[pc];
        g_b1p[net][c] = b1[pc];
        if (c < 32) g_b2[net][c] = b2[c];
    }
}

__device__ __forceinline__ void cp16(void* s, const void* g) {
    unsigned int sa = (unsigned int)__cvta_generic_to_shared(s);
    asm volatile("cp.async.cg.shared.global [%0], [%1], 16;" :: "r"(sa), "l"(g));
}
__device__ __forceinline__ void cp_commit() {
    asm volatile("cp.async.commit_group;");
}
__device__ __forceinline__ void cp_wait_all() {
    asm volatile("cp.async.wait_group 0;");
}
// Explicit counted barriers: legal from divergent call sites.
__device__ __forceinline__ void bar_all() {
    asm volatile("bar.sync 0, %0;" :: "n"(THREADS) : "memory");
}
__device__ __forceinline__ void pair_bar(int pair) {
    asm volatile("bar.sync %0, 64;" :: "r"(pair + 1) : "memory");
}

// Packed dual-fp32 FMA: d = a*b + d (elementwise on the two f32 halves).
__device__ __forceinline__ void ffma2(float2& d, const float2& a, const float2& b) {
    asm("fma.rn.f32x2 %0, %1, %2, %0;"
        : "+l"(reinterpret_cast<unsigned long long&>(d))
        : "l"(reinterpret_cast<const unsigned long long&>(a)),
          "l"(reinterpret_cast<const unsigned long long&>(b)));
}

// One degree-group step (ONE net, RPW=4 rows).
// Lane l owns cols 64e+2l+{0,1}, e in [E0,4). CNT = group size, E0 = off>>6.
template<int CNT, int E0, bool PIPE>
__device__ __forceinline__ void do_step(
    int l, int off, const float2 y2[RPW],
    float2 a0[RPW][4], float2 a1[RPW][4], float2 aout2[2],
    const float* W0p, const float* W1p, const float* W2p,
    float2 (*sH0)[RPW], float2 (*sH1)[2])
{
    // ---- layer 0: a0 += y_j * W0row ----
#pragma unroll
    for (int e = E0; e < 4; e++) {
        float2 wv = *(const float2*)(W0p + 64 * e + 2 * l);
#pragma unroll
        for (int r = 0; r < RPW; r++) ffma2(a0[r][e], wv, y2[r]);
    }
    // finalize h0 group [off, off+CNT) -> sH0[u][r] = {h,h}
#pragma unroll
    for (int e = E0; e < 4; e++) {
        int u0 = 64 * e + 2 * l - off;
        if (u0 >= 0 && u0 < CNT) {
#pragma unroll
            for (int r = 0; r < RPW; r++) {
                float h = fmaxf(a0[r][e].x, 0.f);
                sH0[u0][r] = make_float2(h, h);
            }
        }
        if (u0 + 1 >= 0 && u0 + 1 < CNT) {
#pragma unroll
            for (int r = 0; r < RPW; r++) {
                float h = fmaxf(a0[r][e].y, 0.f);
                sH0[u0 + 1][r] = make_float2(h, h);
            }
        }
    }
    __syncwarp();

    // ---- layer 1: a1 += h0_group @ W1 rows ----
    if (PIPE) {
        float2 wv[2][4];
        float4 hA[2], hB[2];
        {
#pragma unroll
            for (int e = E0; e < 4; e++)
                wv[0][e] = *(const float2*)(W1p + 64 * e + 2 * l);
            hA[0] = *(const float4*)&sH0[0][0];
            hB[0] = *(const float4*)&sH0[0][2];
        }
#pragma unroll
        for (int u = 0; u < CNT; u++) {
            const int cur = u & 1, nxt = cur ^ 1;
            if (u + 1 < CNT) {
                const float* wr = W1p + (u + 1) * 256;
#pragma unroll
                for (int e = E0; e < 4; e++)
                    wv[nxt][e] = *(const float2*)(wr + 64 * e + 2 * l);
                hA[nxt] = *(const float4*)&sH0[u + 1][0];
                hB[nxt] = *(const float4*)&sH0[u + 1][2];
            }
            float2 h0 = make_float2(hA[cur].x, hA[cur].y);
            float2 h1 = make_float2(hA[cur].z, hA[cur].w);
            float2 h2 = make_float2(hB[cur].x, hB[cur].y);
            float2 h3 = make_float2(hB[cur].z, hB[cur].w);
#pragma unroll
            for (int e = E0; e < 4; e++) {
                ffma2(a1[0][e], wv[cur][e], h0);
                ffma2(a1[1][e], wv[cur][e], h1);
                ffma2(a1[2][e], wv[cur][e], h2);
                ffma2(a1[3][e], wv[cur][e], h3);
            }
        }
    } else {
#pragma unroll
        for (int u = 0; u < CNT; u++) {
            const float* wr = W1p + u * 256;
            float2 wv[4];
#pragma unroll
            for (int e = E0; e < 4; e++)
                wv[e] = *(const float2*)(wr + 64 * e + 2 * l);
            float4 hq0 = *(const float4*)&sH0[u][0];  // {h0,h0,h1,h1}
            float4 hq1 = *(const float4*)&sH0[u][2];  // {h2,h2,h3,h3}
            float2 h0 = make_float2(hq0.x, hq0.y);
            float2 h1 = make_float2(hq0.z, hq0.w);
            float2 h2 = make_float2(hq1.x, hq1.y);
            float2 h3 = make_float2(hq1.z, hq1.w);
#pragma unroll
            for (int e = E0; e < 4; e++) {
                ffma2(a1[0][e], wv[e], h0);
                ffma2(a1[1][e], wv[e], h1);
                ffma2(a1[2][e], wv[e], h2);
                ffma2(a1[3][e], wv[e], h3);
            }
        }
    }
    // finalize h1 group -> sH1[u][rp] = {h(2rp), h(2rp+1)}
#pragma unroll
    for (int e = E0; e < 4; e++) {
        int u0 = 64 * e + 2 * l - off;
        if (u0 >= 0 && u0 < CNT) {
#pragma unroll
            for (int rp = 0; rp < 2; rp++)
                sH1[u0][rp] = make_float2(fmaxf(a1[2 * rp][e].x, 0.f),
                                          fmaxf(a1[2 * rp + 1][e].x, 0.f));
        }
        if (u0 + 1 >= 0 && u0 + 1 < CNT) {
#pragma unroll
            for (int rp = 0; rp < 2; rp++)
                sH1[u0 + 1][rp] = make_float2(fmaxf(a1[2 * rp][e].y, 0.f),
                                              fmaxf(a1[2 * rp + 1][e].y, 0.f));
        }
    }
    __syncwarp();

    // ---- layer 2: aout += h1_group @ W2 rows (row-pair packed) ----
#pragma unroll
    for (int u = 0; u < CNT; u++) {
        float wf = W2p[u * 32 + l];
        float2 w2 = make_float2(wf, wf);
#pragma unroll
        for (int rp = 0; rp < 2; rp++)
            ffma2(aout2[rp], sH1[u][rp], w2);
    }
}

// Single-warp prefetch of one step's weights (producer warp only).
template<int CNT, int E0>
__device__ __forceinline__ void prefetch_step_1w(int j, int off, int l, float* SB)
{
    constexpr int KC = 64 - 16 * E0;   // 16B chunks per W0/W1 row
#pragma unroll
    for (int net = 0; net < 2; net++) {
#pragma unroll
        for (int k = 0; k < 2; k++) {
            int q = l + 32 * k;
            if (q < KC)
                cp16(SB + net * 256 + 64 * E0 + 4 * q,
                     &g_W0p[net][j][64 * E0 + 4 * q]);
        }
#pragma unroll
        for (int u = 0; u < CNT; u++) {
#pragma unroll
            for (int k = 0; k < 2; k++) {
                int q = l + 32 * k;
                if (q < KC)
                    cp16(SB + W1OFF + (net * 9 + u) * 256 + 64 * E0 + 4 * q,
                         &g_W1p[net][off + u][64 * E0 + 4 * q]);
            }
        }
#pragma unroll
        for (int m = 0; m < 3; m++) {
            int idx = l + 32 * m;
            if (idx < CNT * 8) {
                int u = idx >> 3, q = idx & 7;
                cp16(SB + W2OFF + (net * 9 + u) * 32 + 4 * q,
                     &g_W2p[net][off + u][4 * q]);
            }
        }
    }
}

__device__ __forceinline__ void dispatch_prefetch_1w(int t, int l, float* SB) {
    const int j = t - 1;
    const int off = (t <= 9) ? 9 * (t - 1) : 72 + 8 * (t - 9);
    if (t <= 8)       prefetch_step_1w<9, 0>(j, off, l, SB);
    else if (t <= 15) prefetch_step_1w<8, 1>(j, off, l, SB);
    else if (t <= 23) prefetch_step_1w<8, 2>(j, off, l, SB);
    else              prefetch_step_1w<8, 3>(j, off, l, SB);
}

// One segment of steps [t0, t1] — consumer side, one net per warp.
template<int CNT, int E0, bool PIPE>
__device__ __forceinline__ void run_segment(
    int t0, int t1, int l, int pair, int net,
    const float2 xr2[2],
    float2 a0[RPW][4], float2 a1[RPW][4], float2 aout2[2],
    float* SW, float2 (*sH0)[RPW], float2 (*sH1)[2],
    float4 (*sD)[NPAIR], float4 (*sI)[NPAIR])
{
    for (int t = t0; t <= t1; ++t) {
        const int j  = t - 1;
        const int tb = t & 1;
        // ---- publish this net's emit contribution (lane j only) ----
        if (net == 0) {
            if (l == j) {
                float4 d;
                d.x = xr2[0].x - aout2[0].x;
                d.y = xr2[0].y - aout2[0].y;
                d.z = xr2[1].x - aout2[1].x;
                d.w = xr2[1].y - aout2[1].y;
                sD[tb][pair] = d;
            }
        } else {
            if (l == j) {
                float4 iv;
                iv.x = __expf(-0.5f * aout2[0].x);
                iv.y = __expf(-0.5f * aout2[0].y);
                iv.z = __expf(-0.5f * aout2[1].x);
                iv.w = __expf(-0.5f * aout2[1].y);
                sI[tb][pair] = iv;
            }
        }

        // odd t: phase barrier (weights for t, t+1 + exchange visible)
        // even t: pair barrier (exchange only)
        if (t & 1) bar_all(); else pair_bar(pair);

        // ---- everyone builds y for the 4 rows ----
        float4 d  = sD[tb][pair];
        float4 iv = sI[tb][pair];
        float2 y2[RPW];
        {
            float yv0 = d.x * iv.x, yv1 = d.y * iv.y;
            float yv2 = d.z * iv.z, yv3 = d.w * iv.w;
            y2[0] = make_float2(yv0, yv0);
            y2[1] = make_float2(yv1, yv1);
            y2[2] = make_float2(yv2, yv2);
            y2[3] = make_float2(yv3, yv3);
        }

        const int off = (t <= 9) ? 9 * (t - 1) : 72 + 8 * (t - 9);
        const float* SB  = SW + ((t - 1) & 3) * STEP_FLOATS;
        const float* W0p = SB + net * 256;
        const float* W1p = SB + W1OFF + net * 2304;
        const float* W2p = SB + W2OFF + net * 288;
        do_step<CNT, E0, PIPE>(l, off, y2, a0, a1, aout2, W0p, W1p, W2p, sH0, sH1);
    }
}

__global__ __launch_bounds__(THREADS, 1)
void afmade_kernel(const float* __restrict__ x, float* __restrict__ out)
{
    // dynamic smem: 4 step slots x STEP_FLOATS
    extern __shared__ __align__(16) unsigned char dynsm[];
    float* SW = (float*)dynsm;

    __shared__ __align__(16) float2 sH0s[NCW][9][RPW];   // per-warp h0 {h,h}
    __shared__ __align__(16) float2 sH1s[NCW][9][2];     // per-warp h1 row pairs
    __shared__ __align__(16) float4 sD[2][NPAIR];        // (x - mu), lane j
    __shared__ __align__(16) float4 sI[2][NPAIR];        // exp(-0.5*lv), lane j
    __shared__ __align__(16) float  sIF[NPAIR][RPW][32]; // final inv, all cols

    const int tid = threadIdx.x;
    const int w   = tid >> 5;
    const int l   = tid & 31;

    if (w == NCW) {
        // ================= producer warp =================
        prefetch_step_1w<9, 0>(0, 0, l, SW);
        prefetch_step_1w<9, 0>(1, 9, l, SW + STEP_FLOATS);
        cp_commit();
        for (int p = 0; p < 16; ++p) {
            cp_wait_all();
            bar_all();                     // phase p data visible to consumers
            if (p < 15) {
                float* NB = SW + (((p + 1) & 1) * 2) * STEP_FLOATS;
                const int t0 = 2 * p + 3;  // first step of phase p+1
                dispatch_prefetch_1w(t0, l, NB);
                if (t0 + 1 <= 31)
                    dispatch_prefetch_1w(t0 + 1, l, NB + STEP_FLOATS);
                cp_commit();
            }
        }
        return;
    }

    // ================= compute warps (7 pairs x {mu, lv}) =================
    const int pair = w >> 1;
    const int net  = w & 1;                  // 0 = mu, 1 = lv
    const int base_row_raw = blockIdx.x * ROWS_PER_BLOCK + pair * RPW;
    const bool valid = (base_row_raw + RPW) <= Bb;   // pair-uniform
    const int base_row = valid ? base_row_raw : 0;

    float2 a0[RPW][4], a1[RPW][4], aout2[2];
    float2 xr2[2];

#pragma unroll
    for (int e = 0; e < 4; e++) {
        float2 b0v = *(const float2*)&g_b0p[net][64 * e + 2 * l];
        float2 b1v = *(const float2*)&g_b1p[net][64 * e + 2 * l];
#pragma unroll
        for (int r = 0; r < RPW; r++) { a0[r][e] = b0v; a1[r][e] = b1v; }
    }
    {
        float b2v = g_b2[net][l];
        aout2[0] = make_float2(b2v, b2v);
        aout2[1] = make_float2(b2v, b2v);
    }
#pragma unroll
    for (int rp = 0; rp < 2; rp++) {
        xr2[rp] = make_float2(x[(base_row + 2 * rp) * 32 + l],
                              x[(base_row + 2 * rp + 1) * 32 + l]);
    }

    // ---- 4 segments; PIPE in the late segments (dead regs pay for it) ----
    run_segment<9, 0, false>( 1,  8, l, pair, net, xr2, a0, a1, aout2,
                              SW, sH0s[w], sH1s[w], sD, sI);
    run_segment<8, 1, false>( 9, 15, l, pair, net, xr2, a0, a1, aout2,
                              SW, sH0s[w], sH1s[w], sD, sI);
    run_segment<8, 2, true >(16, 23, l, pair, net, xr2, a0, a1, aout2,
                              SW, sH0s[w], sH1s[w], sD, sI);
    run_segment<8, 3, true >(24, 31, l, pair, net, xr2, a0, a1, aout2,
                              SW, sH0s[w], sH1s[w], sD, sI);

    // ---- epilogue: every col is final; cross-net combine ----
    if (net == 1) {
        // lv-warp: publish inv for all cols, then reduce logstd
        float ls[RPW];
        ls[0] = 0.5f * aout2[0].x;  ls[1] = 0.5f * aout2[0].y;
        ls[2] = 0.5f * aout2[1].x;  ls[3] = 0.5f * aout2[1].y;
#pragma unroll
        for (int r = 0; r < RPW; r++)
            sIF[pair][r][l] = __expf(-ls[r]);
        pair_bar(pair);
#pragma unroll
        for (int r = 0; r < RPW; r++) {
            float s = ls[r];
#pragma unroll
            for (int o = 16; o > 0; o >>= 1)
                s += __shfl_xor_sync(0xffffffffu, s, o);
            if (l == 0 && valid) out[Bb * Dd + base_row + r] = s;
        }
    } else {
        // mu-warp: y = (x - mu) * inv, coalesced stores
        float d[RPW];
        d[0] = xr2[0].x - aout2[0].x;  d[1] = xr2[0].y - aout2[0].y;
        d[2] = xr2[1].x - aout2[1].x;  d[3] = xr2[1].y - aout2[1].y;
        pair_bar(pair);
        if (valid) {
#pragma unroll
            for (int r = 0; r < RPW; r++)
                out[(base_row + r) * 32 + l] = d[r] * sIF[pair][r][l];
        }
    }
}

extern "C" void kernel_launch(void* const* d_in, const int* in_sizes, int n_in,
                              void* d_out, int out_size)
{
    (void)in_sizes; (void)n_in; (void)out_size;
    const float* x = (const float*)d_in[0];

    prep_kernel<<<512, 256>>>(
        (const float*)d_in[1],  (const float*)d_in[2],  (const float*)d_in[3],
        (const float*)d_in[4],  (const float*)d_in[5],  (const float*)d_in[6],
        (const float*)d_in[7],  (const float*)d_in[8],  (const float*)d_in[9],
        (const float*)d_in[10], (const float*)d_in[11], (const float*)d_in[12]);

    const int dyn_smem = 4 * STEP_FLOATS * 4;   // 91136 B (4 step slots)
    cudaFuncSetAttribute(afmade_kernel,
                         cudaFuncAttributeMaxDynamicSharedMemorySize, dyn_smem);
    afmade_kernel<<<GRID, THREADS, dyn_smem>>>(x, (float*)d_out);
}